// round 2
// baseline (speedup 1.0000x reference)
#include <cuda_runtime.h>
#include <math.h>

#define BATCH   4
#define SEQ     2048
#define DMODEL  768
#define NHEADS  12
#define HDIM    64
#define MTOT    (BATCH*SEQ)   /* 8192 */

// Scratch (static device arrays: allocation-free per harness rules)
__device__ float  g_Q [MTOT*DMODEL];
__device__ float  g_K [MTOT*DMODEL];
__device__ float  g_V [MTOT*DMODEL];
__device__ float  g_AO[MTOT*DMODEL];
__device__ float2 g_tbl[SEQ*(HDIM/2)];   // (cos, sin) per (s, pair)

// ---------------------------------------------------------------------------
// RoPE table: one fp64-accurate sincos per distinct (s, j). 65536 threads.
// Angle computed as fp32 (s * fp32(inv_freq)) to match the reference's fp32
// angle, then sin/cos in double (immune to fast-math substitution).
// ---------------------------------------------------------------------------
__global__ void rope_table_kernel()
{
    int idx = blockIdx.x * blockDim.x + threadIdx.x;
    if (idx >= SEQ * (HDIM/2)) return;
    int s = idx >> 5;           // 0..2047
    int j = idx & 31;           // pair index
    float invf = (float)pow(10000.0, -(double)(2*j) / (double)HDIM);
    float angf = (float)s * invf;
    double sn, cs;
    sincos((double)angf, &sn, &cs);
    g_tbl[idx] = make_float2((float)cs, (float)sn);
}

// ---------------------------------------------------------------------------
// C[M,N] = A[M,K] @ B[N,K]^T  (both K-contiguous row-major)
// 128x128 tile, 256 threads, 8x8 accumulators, K-step 16, register prefetch.
// ROPE: 0 = none, 1 = rope + 0.125 scale (Q), 2 = rope (K).
// Heads are 64 columns wide and tiles are 128-aligned, so every thread's
// 8-column strip lies inside one head and contains whole rope pairs.
// ---------------------------------------------------------------------------
template<int ROPE>
__global__ __launch_bounds__(256) void gemm128_kernel(
    const float* __restrict__ A, const float* __restrict__ B,
    float* __restrict__ C, int M, int N, int K)
{
    __shared__ float As[16][128];
    __shared__ float Bs[16][128];

    const int tid = threadIdx.x;
    const int tx  = tid & 15;        // N direction (8 cols each)
    const int ty  = tid >> 4;        // M direction (8 rows each)
    const int m0  = blockIdx.y * 128;
    const int n0  = blockIdx.x * 128;

    // Loader mapping: 512 float4 per 128x16 tile, 2 per thread.
    const int r0 = tid >> 1;                 // 0..127
    const int c0 = (tid & 1) * 8;            // 0 or 8
    const int r1 = r0;                       // second f4: cols +4
    const int c1 = c0 + 4;

    const float* a0 = A + (size_t)(m0 + r0) * K + c0;
    const float* a1 = A + (size_t)(m0 + r1) * K + c1;
    const float* b0 = B + (size_t)(n0 + r0) * K + c0;
    const float* b1 = B + (size_t)(n0 + r1) * K + c1;

    float acc[8][8] = {};
    float4 pa0, pa1, pb0, pb1;

    pa0 = *(const float4*)(a0);
    pa1 = *(const float4*)(a1);
    pb0 = *(const float4*)(b0);
    pb1 = *(const float4*)(b1);

    for (int k0 = 0; k0 < K; k0 += 16) {
        __syncthreads();   // previous compute done reading smem
        As[c0+0][r0] = pa0.x; As[c0+1][r0] = pa0.y; As[c0+2][r0] = pa0.z; As[c0+3][r0] = pa0.w;
        As[c1+0][r1] = pa1.x; As[c1+1][r1] = pa1.y; As[c1+2][r1] = pa1.z; As[c1+3][r1] = pa1.w;
        Bs[c0+0][r0] = pb0.x; Bs[c0+1][r0] = pb0.y; Bs[c0+2][r0] = pb0.z; Bs[c0+3][r0] = pb0.w;
        Bs[c1+0][r1] = pb1.x; Bs[c1+1][r1] = pb1.y; Bs[c1+2][r1] = pb1.z; Bs[c1+3][r1] = pb1.w;
        __syncthreads();

        if (k0 + 16 < K) {   // prefetch next tile (latency hidden by compute)
            pa0 = *(const float4*)(a0 + k0 + 16);
            pa1 = *(const float4*)(a1 + k0 + 16);
            pb0 = *(const float4*)(b0 + k0 + 16);
            pb1 = *(const float4*)(b1 + k0 + 16);
        }

        #pragma unroll
        for (int kk = 0; kk < 16; kk++) {
            float a[8], b[8];
            *(float4*)&a[0] = *(const float4*)&As[kk][ty*8];
            *(float4*)&a[4] = *(const float4*)&As[kk][ty*8+4];
            *(float4*)&b[0] = *(const float4*)&Bs[kk][tx*8];
            *(float4*)&b[4] = *(const float4*)&Bs[kk][tx*8+4];
            #pragma unroll
            for (int i = 0; i < 8; i++)
                #pragma unroll
                for (int j = 0; j < 8; j++)
                    acc[i][j] += a[i] * b[j];
        }
    }

    const int cbase = n0 + tx * 8;
    if (ROPE != 0) {
        const int pbase = (cbase & (HDIM-1)) >> 1;  // first rope pair in strip
        #pragma unroll
        for (int i = 0; i < 8; i++) {
            const int s = (m0 + ty*8 + i) & (SEQ - 1);
            const float2* trow = &g_tbl[s * (HDIM/2) + pbase];
            #pragma unroll
            for (int p = 0; p < 4; p++) {
                float2 cs = trow[p];
                float v1 = acc[i][2*p], v2 = acc[i][2*p+1];
                float r1 = v1*cs.x - v2*cs.y;
                float r2 = v1*cs.y + v2*cs.x;
                if (ROPE == 1) { r1 *= 0.125f; r2 *= 0.125f; }
                acc[i][2*p]   = r1;
                acc[i][2*p+1] = r2;
            }
        }
    }

    #pragma unroll
    for (int i = 0; i < 8; i++) {
        float* crow = C + (size_t)(m0 + ty*8 + i) * N + cbase;
        *(float4*)(crow)     = make_float4(acc[i][0], acc[i][1], acc[i][2], acc[i][3]);
        *(float4*)(crow + 4) = make_float4(acc[i][4], acc[i][5], acc[i][6], acc[i][7]);
    }
}

// ---------------------------------------------------------------------------
// Causal flash attention, fp32 (unchanged from round 1 — separable in ncu).
// ---------------------------------------------------------------------------
__global__ __launch_bounds__(128) void attn_kernel()
{
    __shared__ float Ks[32][64];
    __shared__ float Vs[32][64];
    __shared__ float Sc[32][128];

    const int t  = threadIdx.x;
    const int bh = blockIdx.y;
    const int b  = bh / NHEADS;
    const int h  = bh % NHEADS;
    const int q0 = blockIdx.x * 128;
    const int qrow = q0 + t;
    const size_t headbase = (size_t)(b * SEQ) * DMODEL + h * HDIM;

    float4 q[16];
    #pragma unroll
    for (int d = 0; d < 16; d++)
        q[d] = *(const float4*)&g_Q[headbase + (size_t)qrow * DMODEL + d*4];

    float4 o[16];
    #pragma unroll
    for (int d = 0; d < 16; d++) o[d] = make_float4(0.f, 0.f, 0.f, 0.f);

    float m = -INFINITY, l = 0.f;

    const int ktiles = (q0 + 128) >> 5;
    for (int kt = 0; kt < ktiles; kt++) {
        const int kb = kt << 5;

        #pragma unroll
        for (int i = 0; i < 4; i++) {
            int idx = t + i * 128;
            int r = idx >> 4, c = (idx & 15) * 4;
            *(float4*)&Ks[r][c] = *(const float4*)&g_K[headbase + (size_t)(kb + r) * DMODEL + c];
            *(float4*)&Vs[r][c] = *(const float4*)&g_V[headbase + (size_t)(kb + r) * DMODEL + c];
        }
        __syncthreads();

        float mt = m;
        #pragma unroll 4
        for (int j = 0; j < 32; j++) {
            float sx = 0.f, sy = 0.f, sz = 0.f, sw = 0.f;
            #pragma unroll
            for (int d = 0; d < 16; d++) {
                float4 kv = *(const float4*)&Ks[j][d*4];
                sx += q[d].x * kv.x;  sy += q[d].y * kv.y;
                sz += q[d].z * kv.z;  sw += q[d].w * kv.w;
            }
            float sc = (sx + sy) + (sz + sw);
            sc = (kb + j <= qrow) ? sc : -1e30f;
            Sc[j][t] = sc;
            mt = fmaxf(mt, sc);
        }

        float corr = __expf(m - mt);
        m = mt;
        l *= corr;
        #pragma unroll
        for (int d = 0; d < 16; d++) {
            o[d].x *= corr; o[d].y *= corr; o[d].z *= corr; o[d].w *= corr;
        }

        #pragma unroll 4
        for (int j = 0; j < 32; j++) {
            float p = __expf(Sc[j][t] - m);
            l += p;
            #pragma unroll
            for (int d = 0; d < 16; d++) {
                float4 vv = *(const float4*)&Vs[j][d*4];
                o[d].x += p * vv.x; o[d].y += p * vv.y;
                o[d].z += p * vv.z; o[d].w += p * vv.w;
            }
        }
        __syncthreads();
    }

    const float invl = 1.f / l;
    #pragma unroll
    for (int d = 0; d < 16; d++) {
        float4 r = make_float4(o[d].x*invl, o[d].y*invl, o[d].z*invl, o[d].w*invl);
        *(float4*)&g_AO[headbase + (size_t)qrow * DMODEL + d*4] = r;
    }
}

// ---------------------------------------------------------------------------
extern "C" void kernel_launch(void* const* d_in, const int* in_sizes, int n_in,
                              void* d_out, int out_size)
{
    const float* x  = (const float*)d_in[0];
    const float* wq = (const float*)d_in[1];
    const float* wk = (const float*)d_in[2];
    const float* wv = (const float*)d_in[3];
    const float* wo = (const float*)d_in[4];
    float* out = (float*)d_out;

    float *Q, *K, *V, *AO;
    cudaGetSymbolAddress((void**)&Q,  g_Q);
    cudaGetSymbolAddress((void**)&K,  g_K);
    cudaGetSymbolAddress((void**)&V,  g_V);
    cudaGetSymbolAddress((void**)&AO, g_AO);

    rope_table_kernel<<<(SEQ*(HDIM/2) + 255)/256, 256>>>();

    dim3 gblk(256);
    dim3 ggrid(DMODEL/128, MTOT/128);   // (6, 64)

    gemm128_kernel<1><<<ggrid, gblk>>>(x, wq, Q, MTOT, DMODEL, DMODEL);
    gemm128_kernel<2><<<ggrid, gblk>>>(x, wk, K, MTOT, DMODEL, DMODEL);
    gemm128_kernel<0><<<ggrid, gblk>>>(x, wv, V, MTOT, DMODEL, DMODEL);

    attn_kernel<<<dim3(SEQ/128, BATCH*NHEADS), 128>>>();

    gemm128_kernel<0><<<ggrid, gblk>>>(AO, wo, out, MTOT, DMODEL, DMODEL);
}

// round 4
// speedup vs baseline: 1.3276x; 1.3276x over previous
#include <cuda_runtime.h>
#include <math.h>

#define BATCH   4
#define SEQ     2048
#define DMODEL  768
#define NHEADS  12
#define HDIM    64
#define MTOT    (BATCH*SEQ)   /* 8192 */

// Scratch (static device arrays: allocation-free per harness rules)
__device__ float  g_Q [MTOT*DMODEL];
__device__ float  g_K [MTOT*DMODEL];
__device__ float  g_V [MTOT*DMODEL];
__device__ float  g_AO[MTOT*DMODEL];
__device__ float2 g_tbl[SEQ*(HDIM/2)];   // (cos, sin) per (s, pair)

// ---------------------------------------------------------------------------
// RoPE table: one fp64-accurate sincos per distinct (s, j). Split into two
// launches (s-range) so attn_kernel is launch #6 — the one ncu -s 5 captures.
// ---------------------------------------------------------------------------
__global__ void rope_table_kernel(int s_base)
{
    int idx = blockIdx.x * blockDim.x + threadIdx.x;
    if (idx >= (SEQ/2) * (HDIM/2)) return;
    int s = s_base + (idx >> 5);
    int j = idx & 31;
    float invf = (float)pow(10000.0, -(double)(2*j) / (double)HDIM);
    float angf = (float)s * invf;
    double sn, cs;
    sincos((double)angf, &sn, &cs);
    g_tbl[s * (HDIM/2) + j] = make_float2((float)cs, (float)sn);
}

// ---------------------------------------------------------------------------
// C[M,N] = A[M,K] @ B[N,K]^T  (both K-contiguous row-major)
// 64x64 tile (conflict-free LDS, high occupancy), 256 threads,
// 4x4 accumulators, K-step 16. ROPE: 0 none, 1 rope+0.125 (Q), 2 rope (K).
// ---------------------------------------------------------------------------
template<int ROPE>
__global__ __launch_bounds__(256) void gemm_abt_kernel(
    const float* __restrict__ A, const float* __restrict__ B,
    float* __restrict__ C, int M, int N, int K)
{
    __shared__ float As[16][64];
    __shared__ float Bs[16][64];

    const int tid = threadIdx.x;
    const int tx  = tid & 15;       // 0..15  (N direction)
    const int ty  = tid >> 4;       // 0..15  (M direction)
    const int m0  = blockIdx.y * 64;
    const int n0  = blockIdx.x * 64;
    const int lrow = tid >> 2;      // 0..63
    const int lc4  = tid & 3;       // 0..3

    float acc[4][4] = {};

    const float* aptr = A + (size_t)(m0 + lrow) * K + lc4 * 4;
    const float* bptr = B + (size_t)(n0 + lrow) * K + lc4 * 4;

    for (int k0 = 0; k0 < K; k0 += 16) {
        float4 av = *(const float4*)(aptr + k0);
        float4 bv = *(const float4*)(bptr + k0);
        As[lc4*4+0][lrow] = av.x; As[lc4*4+1][lrow] = av.y;
        As[lc4*4+2][lrow] = av.z; As[lc4*4+3][lrow] = av.w;
        Bs[lc4*4+0][lrow] = bv.x; Bs[lc4*4+1][lrow] = bv.y;
        Bs[lc4*4+2][lrow] = bv.z; Bs[lc4*4+3][lrow] = bv.w;
        __syncthreads();

        #pragma unroll
        for (int kk = 0; kk < 16; kk++) {
            float4 a = *(const float4*)&As[kk][ty*4];
            float4 b = *(const float4*)&Bs[kk][tx*4];
            acc[0][0] += a.x*b.x; acc[0][1] += a.x*b.y; acc[0][2] += a.x*b.z; acc[0][3] += a.x*b.w;
            acc[1][0] += a.y*b.x; acc[1][1] += a.y*b.y; acc[1][2] += a.y*b.z; acc[1][3] += a.y*b.w;
            acc[2][0] += a.z*b.x; acc[2][1] += a.z*b.y; acc[2][2] += a.z*b.z; acc[2][3] += a.z*b.w;
            acc[3][0] += a.w*b.x; acc[3][1] += a.w*b.y; acc[3][2] += a.w*b.z; acc[3][3] += a.w*b.w;
        }
        __syncthreads();
    }

    const int cbase = n0 + tx * 4;
    if (ROPE != 0) {
        const int pbase = (cbase & (HDIM-1)) >> 1;   // first rope pair in strip
        #pragma unroll
        for (int i = 0; i < 4; i++) {
            const int s = (m0 + ty*4 + i) & (SEQ - 1);
            const float2* trow = &g_tbl[s * (HDIM/2) + pbase];
            #pragma unroll
            for (int p = 0; p < 2; p++) {
                float2 cs = trow[p];
                float v1 = acc[i][2*p], v2 = acc[i][2*p+1];
                float r1 = v1*cs.x - v2*cs.y;
                float r2 = v1*cs.y + v2*cs.x;
                if (ROPE == 1) { r1 *= 0.125f; r2 *= 0.125f; }
                acc[i][2*p]   = r1;
                acc[i][2*p+1] = r2;
            }
        }
    }

    #pragma unroll
    for (int i = 0; i < 4; i++) {
        float4 r = make_float4(acc[i][0], acc[i][1], acc[i][2], acc[i][3]);
        *(float4*)&C[(size_t)(m0 + ty*4 + i) * N + cbase] = r;
    }
}

// ---------------------------------------------------------------------------
// Causal flash attention, fp32. One q row per thread; K/V tiles (32x64) in
// shared; scores staged in Sc[j][t]. Each CTA processes TWO q-strips, bx and
// 15-bx (uniform 68 k-tiles per CTA). Next K/V half-tile prefetched into
// registers. Grid: (8, 48), 128 threads.
// FIX vs round 3: initial tile-0 prefetch row mapping now matches the store
// (rows lr + i*16, not lr + i*8).
// ---------------------------------------------------------------------------
__global__ __launch_bounds__(128) void attn_kernel()
{
    __shared__ float Ks[32][64];
    __shared__ float Vs[32][64];
    __shared__ float Sc[32][128];

    const int t  = threadIdx.x;
    const int bh = blockIdx.y;
    const int b  = bh / NHEADS;
    const int h  = bh % NHEADS;
    const size_t headbase = (size_t)(b * SEQ) * DMODEL + h * HDIM;

    const int lr = t >> 4;            // loader row 0..7
    const int lc = (t & 15) * 4;      // loader col 0..60

    for (int sidx = 0; sidx < 2; sidx++) {
        const int bx = (sidx == 0) ? (int)blockIdx.x : (15 - (int)blockIdx.x);
        const int q0 = bx * 128;
        const int qrow = q0 + t;

        float4 q[16];
        #pragma unroll
        for (int d = 0; d < 16; d++)
            q[d] = *(const float4*)&g_Q[headbase + (size_t)qrow * DMODEL + d*4];

        float4 o[16];
        #pragma unroll
        for (int d = 0; d < 16; d++) o[d] = make_float4(0.f, 0.f, 0.f, 0.f);

        float m = -INFINITY, l = 0.f;

        const int ktiles = (q0 + 128) >> 5;

        // Prefetch tile 0 (rows lr, lr+16 — MUST match the store mapping).
        float4 pk[2], pv[2];
        #pragma unroll
        for (int i = 0; i < 2; i++) {
            const size_t src = headbase + (size_t)(lr + i*16) * DMODEL + lc;
            pk[i] = *(const float4*)&g_K[src];
            pv[i] = *(const float4*)&g_V[src];
        }

        for (int kt = 0; kt < ktiles; kt++) {
            __syncthreads();   // previous tile's compute done with smem
            #pragma unroll
            for (int i = 0; i < 2; i++) {
                *(float4*)&Ks[lr + i*16][lc] = pk[i];     // rows 0..7, 16..23
                *(float4*)&Vs[lr + i*16][lc] = pv[i];
            }
            #pragma unroll
            for (int i = 0; i < 2; i++) {                  // rows 8..15, 24..31
                const size_t src = headbase + (size_t)((kt<<5) + lr + 8 + i*16) * DMODEL + lc;
                *(float4*)&Ks[lr + 8 + i*16][lc] = *(const float4*)&g_K[src];
                *(float4*)&Vs[lr + 8 + i*16][lc] = *(const float4*)&g_V[src];
            }
            __syncthreads();

            if (kt + 1 < ktiles) {   // prefetch next tile's rows lr, lr+16
                #pragma unroll
                for (int i = 0; i < 2; i++) {
                    const size_t src = headbase + (size_t)(((kt+1)<<5) + lr + i*16) * DMODEL + lc;
                    pk[i] = *(const float4*)&g_K[src];
                    pv[i] = *(const float4*)&g_V[src];
                }
            }

            const int kb = kt << 5;
            float mt = m;
            #pragma unroll 4
            for (int j = 0; j < 32; j++) {
                float sx = 0.f, sy = 0.f, sz = 0.f, sw = 0.f;
                #pragma unroll
                for (int d = 0; d < 16; d++) {
                    float4 kv = *(const float4*)&Ks[j][d*4];
                    sx += q[d].x * kv.x;  sy += q[d].y * kv.y;
                    sz += q[d].z * kv.z;  sw += q[d].w * kv.w;
                }
                float sc = (sx + sy) + (sz + sw);      // scale folded into q
                sc = (kb + j <= qrow) ? sc : -1e30f;   // causal mask
                Sc[j][t] = sc;
                mt = fmaxf(mt, sc);
            }

            float corr = __expf(m - mt);
            m = mt;
            l *= corr;
            #pragma unroll
            for (int d = 0; d < 16; d++) {
                o[d].x *= corr; o[d].y *= corr; o[d].z *= corr; o[d].w *= corr;
            }

            #pragma unroll 4
            for (int j = 0; j < 32; j++) {
                float p = __expf(Sc[j][t] - m);
                l += p;
                #pragma unroll
                for (int d = 0; d < 16; d++) {
                    float4 vv = *(const float4*)&Vs[j][d*4];
                    o[d].x += p * vv.x; o[d].y += p * vv.y;
                    o[d].z += p * vv.z; o[d].w += p * vv.w;
                }
            }
        }

        const float invl = 1.f / l;
        #pragma unroll
        for (int d = 0; d < 16; d++) {
            float4 r = make_float4(o[d].x*invl, o[d].y*invl, o[d].z*invl, o[d].w*invl);
            *(float4*)&g_AO[headbase + (size_t)qrow * DMODEL + d*4] = r;
        }
        __syncthreads();   // smem reuse safety before next strip
    }
}

// ---------------------------------------------------------------------------
extern "C" void kernel_launch(void* const* d_in, const int* in_sizes, int n_in,
                              void* d_out, int out_size)
{
    const float* x  = (const float*)d_in[0];
    const float* wq = (const float*)d_in[1];
    const float* wk = (const float*)d_in[2];
    const float* wv = (const float*)d_in[3];
    const float* wo = (const float*)d_in[4];
    float* out = (float*)d_out;

    float *Q, *K, *V, *AO;
    cudaGetSymbolAddress((void**)&Q,  g_Q);
    cudaGetSymbolAddress((void**)&K,  g_K);
    cudaGetSymbolAddress((void**)&V,  g_V);
    cudaGetSymbolAddress((void**)&AO, g_AO);

    // Two table halves (launches #1-#2) so attn is launch #6 for ncu -s 5.
    const int tblk = ((SEQ/2)*(HDIM/2) + 255) / 256;
    rope_table_kernel<<<tblk, 256>>>(0);
    rope_table_kernel<<<tblk, 256>>>(SEQ/2);

    dim3 gblk(256);
    dim3 ggrid(DMODEL/64, MTOT/64);   // (12, 128)

    gemm_abt_kernel<1><<<ggrid, gblk>>>(x, wq, Q, MTOT, DMODEL, DMODEL);
    gemm_abt_kernel<2><<<ggrid, gblk>>>(x, wk, K, MTOT, DMODEL, DMODEL);
    gemm_abt_kernel<0><<<ggrid, gblk>>>(x, wv, V, MTOT, DMODEL, DMODEL);

    attn_kernel<<<dim3(SEQ/256, BATCH*NHEADS), 128>>>();   // launch #6

    gemm_abt_kernel<0><<<ggrid, gblk>>>(AO, wo, out, MTOT, DMODEL, DMODEL);
}

// round 6
// speedup vs baseline: 1.8931x; 1.4260x over previous
#include <cuda_runtime.h>
#include <cuda_bf16.h>
#include <math.h>
#include <cstdint>

#define BATCH   4
#define SEQ     2048
#define DMODEL  768
#define NHEADS  12
#define HDIM    64
#define MTOT    (BATCH*SEQ)   /* 8192 */
#define WSZ     (DMODEL*DMODEL)

// Scratch (static device arrays: allocation-free per harness rules)
__device__ float  g_Q [MTOT*DMODEL];
__device__ float  g_K [MTOT*DMODEL];
__device__ float  g_V [MTOT*DMODEL];
__device__ float  g_AO[MTOT*DMODEL];
__device__ float2 g_tbl[SEQ*(HDIM/2)];
__device__ __nv_bfloat16 g_xh[MTOT*DMODEL];   // hi split of activations (x, later AO)
__device__ __nv_bfloat16 g_xl[MTOT*DMODEL];   // lo split
__device__ __nv_bfloat16 g_wh[4*WSZ];         // hi split of wq,wk,wv,wo
__device__ __nv_bfloat16 g_wl[4*WSZ];

// ===========================================================================
// Helpers
// ===========================================================================
__device__ __forceinline__ uint32_t smem_u32(const void* p) {
    uint32_t a;
    asm("{ .reg .u64 t; cvta.to.shared.u64 t, %1; cvt.u32.u64 %0, t; }" : "=r"(a) : "l"(p));
    return a;
}
__device__ __forceinline__ void ldsm4(uint32_t* r, uint32_t addr) {
    asm volatile("ldmatrix.sync.aligned.m8n8.x4.shared.b16 {%0,%1,%2,%3}, [%4];"
        : "=r"(r[0]), "=r"(r[1]), "=r"(r[2]), "=r"(r[3]) : "r"(addr));
}
__device__ __forceinline__ void mma16816(float* c, const uint32_t* a, uint32_t b0, uint32_t b1) {
    asm volatile("mma.sync.aligned.m16n8k16.row.col.f32.bf16.bf16.f32 "
        "{%0,%1,%2,%3}, {%4,%5,%6,%7}, {%8,%9}, {%0,%1,%2,%3};"
        : "+f"(c[0]), "+f"(c[1]), "+f"(c[2]), "+f"(c[3])
        : "r"(a[0]), "r"(a[1]), "r"(a[2]), "r"(a[3]), "r"(b0), "r"(b1));
}
__device__ __forceinline__ uint32_t pack2(float x, float y) {
    __nv_bfloat16 hx = __float2bfloat16(x), hy = __float2bfloat16(y);
    return (uint32_t)__bfloat16_as_ushort(hx) | ((uint32_t)__bfloat16_as_ushort(hy) << 16);
}

// ---------------------------------------------------------------------------
// RoPE table (fp64-accurate sincos, 65536 entries, one launch)
// ---------------------------------------------------------------------------
__global__ void rope_table_kernel()
{
    int idx = blockIdx.x * blockDim.x + threadIdx.x;
    if (idx >= SEQ * (HDIM/2)) return;
    int s = idx >> 5, j = idx & 31;
    float invf = (float)pow(10000.0, -(double)(2*j) / (double)HDIM);
    float angf = (float)s * invf;
    double sn, cs;
    sincos((double)angf, &sn, &cs);
    g_tbl[idx] = make_float2((float)cs, (float)sn);
}

// ---------------------------------------------------------------------------
// hi/lo bf16 split kernels (bandwidth-bound, float4 vectorized)
// ---------------------------------------------------------------------------
__device__ __forceinline__ void split4(float4 v, uint2& hi, uint2& lo)
{
    __nv_bfloat16 h0 = __float2bfloat16(v.x), h1 = __float2bfloat16(v.y);
    __nv_bfloat16 h2 = __float2bfloat16(v.z), h3 = __float2bfloat16(v.w);
    hi.x = (uint32_t)__bfloat16_as_ushort(h0) | ((uint32_t)__bfloat16_as_ushort(h1) << 16);
    hi.y = (uint32_t)__bfloat16_as_ushort(h2) | ((uint32_t)__bfloat16_as_ushort(h3) << 16);
    lo.x = pack2(v.x - __bfloat162float(h0), v.y - __bfloat162float(h1));
    lo.y = pack2(v.z - __bfloat162float(h2), v.w - __bfloat162float(h3));
}

__global__ void split_kernel(const float* __restrict__ src,
                             __nv_bfloat16* __restrict__ hi,
                             __nv_bfloat16* __restrict__ lo, int n4)
{
    int i = blockIdx.x * blockDim.x + threadIdx.x;
    if (i >= n4) return;
    uint2 h, l;
    split4(((const float4*)src)[i], h, l);
    ((uint2*)hi)[i] = h;
    ((uint2*)lo)[i] = l;
}

__global__ void split4w_kernel(const float* __restrict__ w0, const float* __restrict__ w1,
                               const float* __restrict__ w2, const float* __restrict__ w3)
{
    const int per = WSZ / 4;     // float4s per weight matrix
    int i = blockIdx.x * blockDim.x + threadIdx.x;
    if (i >= 4 * per) return;
    int ws = i / per, off = i - ws * per;
    const float* src = (ws == 0) ? w0 : (ws == 1) ? w1 : (ws == 2) ? w2 : w3;
    uint2 h, l;
    split4(((const float4*)src)[off], h, l);
    ((uint2*)g_wh)[i] = h;
    ((uint2*)g_wl)[i] = l;
}

// ===========================================================================
// Split-bf16 tensor-core GEMM via mma.sync: C[M,768] = A[M,768] @ W[768,768]^T
// C ≈ Ah·Wh + Ah·Wl + Al·Wh.  CTA tile 128x128, 8 warps (2x4), warp 64x32.
// K staged in 32-col chunks; smem rows stride 80B (conflict-free ldmatrix).
// ROPE: 0 none, 1 rope+0.125 (Q), 2 rope (K).
// ===========================================================================
#define SROW 80   /* bytes per 32-col bf16 smem row (64 data + 16 pad) */

template<int ROPE>
__global__ __launch_bounds__(256) void gemm_mma_kernel(
    const __nv_bfloat16* __restrict__ Ah, const __nv_bfloat16* __restrict__ Al,
    const __nv_bfloat16* __restrict__ Bh, const __nv_bfloat16* __restrict__ Bl,
    float* __restrict__ C)
{
    __shared__ __align__(16) char sm[4 * 128 * SROW];   // AH | AL | BH | BL
    const uint32_t sAH = smem_u32(sm);
    const uint32_t sAL = sAH + 128 * SROW;
    const uint32_t sBH = sAL + 128 * SROW;
    const uint32_t sBL = sBH + 128 * SROW;

    const int tid  = threadIdx.x;
    const int wid  = tid >> 5, lane = tid & 31;
    const int wm   = wid >> 2, wn = wid & 3;
    const int m0   = blockIdx.y * 128;
    const int n0   = blockIdx.x * 128;

    // Loader mapping: row r (0..127), col half ch (0 or 16)
    const int r  = tid >> 1;
    const int ch = (tid & 1) * 16;
    const __nv_bfloat16* gAh = Ah + (size_t)(m0 + r) * DMODEL + ch;
    const __nv_bfloat16* gAl = Al + (size_t)(m0 + r) * DMODEL + ch;
    const __nv_bfloat16* gBh = Bh + (size_t)(n0 + r) * DMODEL + ch;
    const __nv_bfloat16* gBl = Bl + (size_t)(n0 + r) * DMODEL + ch;
    const uint32_t soff = (uint32_t)(r * SROW + ch * 2);

    float acc[4][4][4] = {};

    // Fragment smem addresses (lane-dependent, chunk-invariant parts)
    const uint32_t a_row = wm * 64 + (lane & 15);          // + mf*16
    const uint32_t a_colb = (lane >> 4) * 16;              // byte offset of k-half (8 cols * 2B)
    const uint32_t b_row = wn * 32 + (lane & 7) + ((lane >> 4) << 3);  // + nh*16
    const uint32_t b_colb = ((lane >> 3) & 1) * 16;

    for (int kc = 0; kc < DMODEL; kc += 32) {
        __syncthreads();
        *(uint4*)(sm + (sAH - smem_u32(sm)) + soff)      = *(const uint4*)(gAh + kc);
        *(uint4*)(sm + (sAH - smem_u32(sm)) + soff + 16) = *(const uint4*)(gAh + kc + 8);
        *(uint4*)(sm + (sAL - smem_u32(sm)) + soff)      = *(const uint4*)(gAl + kc);
        *(uint4*)(sm + (sAL - smem_u32(sm)) + soff + 16) = *(const uint4*)(gAl + kc + 8);
        *(uint4*)(sm + (sBH - smem_u32(sm)) + soff)      = *(const uint4*)(gBh + kc);
        *(uint4*)(sm + (sBH - smem_u32(sm)) + soff + 16) = *(const uint4*)(gBh + kc + 8);
        *(uint4*)(sm + (sBL - smem_u32(sm)) + soff)      = *(const uint4*)(gBl + kc);
        *(uint4*)(sm + (sBL - smem_u32(sm)) + soff + 16) = *(const uint4*)(gBl + kc + 8);
        __syncthreads();

        #pragma unroll
        for (int ks = 0; ks < 2; ks++) {
            const uint32_t kb = ks * 32;   // byte offset of k16 within chunk
            #pragma unroll
            for (int pass = 0; pass < 3; pass++) {
                const uint32_t aBase = (pass == 2) ? sAL : sAH;
                const uint32_t bBase = (pass == 1) ? sBL : sBH;

                uint32_t afr[4][4];
                #pragma unroll
                for (int mf = 0; mf < 4; mf++)
                    ldsm4(afr[mf], aBase + (a_row + mf*16) * SROW + kb + a_colb);

                uint32_t bfr[2][4];
                #pragma unroll
                for (int nh = 0; nh < 2; nh++)
                    ldsm4(bfr[nh], bBase + (b_row + nh*16) * SROW + kb + b_colb);

                #pragma unroll
                for (int mf = 0; mf < 4; mf++) {
                    #pragma unroll
                    for (int nh = 0; nh < 2; nh++) {
                        mma16816(acc[mf][2*nh],   afr[mf], bfr[nh][0], bfr[nh][1]);
                        mma16816(acc[mf][2*nh+1], afr[mf], bfr[nh][2], bfr[nh][3]);
                    }
                }
            }
        }
    }

    // Epilogue: lane holds rows (g, g+8), cols (2c, 2c+1) per fragment.
    const int lrow = lane >> 2;
    const int lcol = (lane & 3) * 2;
    #pragma unroll
    for (int mf = 0; mf < 4; mf++) {
        #pragma unroll
        for (int nf = 0; nf < 4; nf++) {
            float* c = acc[mf][nf];
            const int col = n0 + wn*32 + nf*8 + lcol;
            #pragma unroll
            for (int half = 0; half < 2; half++) {
                const int m = m0 + wm*64 + mf*16 + lrow + half*8;
                float v1 = c[half*2], v2 = c[half*2+1];
                if (ROPE != 0) {
                    const int s = m & (SEQ - 1);
                    float2 cs = g_tbl[s * (HDIM/2) + ((col & (HDIM-1)) >> 1)];
                    float r1 = v1*cs.x - v2*cs.y;
                    float r2 = v1*cs.y + v2*cs.x;
                    if (ROPE == 1) { r1 *= 0.125f; r2 *= 0.125f; }
                    v1 = r1; v2 = r2;
                }
                *(float2*)&C[(size_t)m * DMODEL + col] = make_float2(v1, v2);
            }
        }
    }
}

// ---------------------------------------------------------------------------
// Causal flash attention, fp32 (unchanged from round 4).
// ---------------------------------------------------------------------------
__global__ __launch_bounds__(128) void attn_kernel()
{
    __shared__ float Ks[32][64];
    __shared__ float Vs[32][64];
    __shared__ float Sc[32][128];

    const int t  = threadIdx.x;
    const int bh = blockIdx.y;
    const int b  = bh / NHEADS;
    const int h  = bh % NHEADS;
    const size_t headbase = (size_t)(b * SEQ) * DMODEL + h * HDIM;

    const int lr = t >> 4;
    const int lc = (t & 15) * 4;

    for (int sidx = 0; sidx < 2; sidx++) {
        const int bx = (sidx == 0) ? (int)blockIdx.x : (15 - (int)blockIdx.x);
        const int q0 = bx * 128;
        const int qrow = q0 + t;

        float4 q[16];
        #pragma unroll
        for (int d = 0; d < 16; d++)
            q[d] = *(const float4*)&g_Q[headbase + (size_t)qrow * DMODEL + d*4];

        float4 o[16];
        #pragma unroll
        for (int d = 0; d < 16; d++) o[d] = make_float4(0.f, 0.f, 0.f, 0.f);

        float m = -INFINITY, l = 0.f;
        const int ktiles = (q0 + 128) >> 5;

        float4 pk[2], pv[2];
        #pragma unroll
        for (int i = 0; i < 2; i++) {
            const size_t src = headbase + (size_t)(lr + i*16) * DMODEL + lc;
            pk[i] = *(const float4*)&g_K[src];
            pv[i] = *(const float4*)&g_V[src];
        }

        for (int kt = 0; kt < ktiles; kt++) {
            __syncthreads();
            #pragma unroll
            for (int i = 0; i < 2; i++) {
                *(float4*)&Ks[lr + i*16][lc] = pk[i];
                *(float4*)&Vs[lr + i*16][lc] = pv[i];
            }
            #pragma unroll
            for (int i = 0; i < 2; i++) {
                const size_t src = headbase + (size_t)((kt<<5) + lr + 8 + i*16) * DMODEL + lc;
                *(float4*)&Ks[lr + 8 + i*16][lc] = *(const float4*)&g_K[src];
                *(float4*)&Vs[lr + 8 + i*16][lc] = *(const float4*)&g_V[src];
            }
            __syncthreads();

            if (kt + 1 < ktiles) {
                #pragma unroll
                for (int i = 0; i < 2; i++) {
                    const size_t src = headbase + (size_t)(((kt+1)<<5) + lr + i*16) * DMODEL + lc;
                    pk[i] = *(const float4*)&g_K[src];
                    pv[i] = *(const float4*)&g_V[src];
                }
            }

            const int kb = kt << 5;
            float mt = m;
            #pragma unroll 4
            for (int j = 0; j < 32; j++) {
                float sx = 0.f, sy = 0.f, sz = 0.f, sw = 0.f;
                #pragma unroll
                for (int d = 0; d < 16; d++) {
                    float4 kv = *(const float4*)&Ks[j][d*4];
                    sx += q[d].x * kv.x;  sy += q[d].y * kv.y;
                    sz += q[d].z * kv.z;  sw += q[d].w * kv.w;
                }
                float sc = (sx + sy) + (sz + sw);
                sc = (kb + j <= qrow) ? sc : -1e30f;
                Sc[j][t] = sc;
                mt = fmaxf(mt, sc);
            }

            float corr = __expf(m - mt);
            m = mt;
            l *= corr;
            #pragma unroll
            for (int d = 0; d < 16; d++) {
                o[d].x *= corr; o[d].y *= corr; o[d].z *= corr; o[d].w *= corr;
            }

            #pragma unroll 4
            for (int j = 0; j < 32; j++) {
                float p = __expf(Sc[j][t] - m);
                l += p;
                #pragma unroll
                for (int d = 0; d < 16; d++) {
                    float4 vv = *(const float4*)&Vs[j][d*4];
                    o[d].x += p * vv.x; o[d].y += p * vv.y;
                    o[d].z += p * vv.z; o[d].w += p * vv.w;
                }
            }
        }

        const float invl = 1.f / l;
        #pragma unroll
        for (int d = 0; d < 16; d++) {
            float4 r = make_float4(o[d].x*invl, o[d].y*invl, o[d].z*invl, o[d].w*invl);
            *(float4*)&g_AO[headbase + (size_t)qrow * DMODEL + d*4] = r;
        }
        __syncthreads();
    }
}

// ---------------------------------------------------------------------------
extern "C" void kernel_launch(void* const* d_in, const int* in_sizes, int n_in,
                              void* d_out, int out_size)
{
    const float* x  = (const float*)d_in[0];
    const float* wq = (const float*)d_in[1];
    const float* wk = (const float*)d_in[2];
    const float* wv = (const float*)d_in[3];
    const float* wo = (const float*)d_in[4];
    float* out = (float*)d_out;

    float *Q, *K, *V, *AO;
    __nv_bfloat16 *XH, *XL, *WH, *WL;
    cudaGetSymbolAddress((void**)&Q,  g_Q);
    cudaGetSymbolAddress((void**)&K,  g_K);
    cudaGetSymbolAddress((void**)&V,  g_V);
    cudaGetSymbolAddress((void**)&AO, g_AO);
    cudaGetSymbolAddress((void**)&XH, g_xh);
    cudaGetSymbolAddress((void**)&XL, g_xl);
    cudaGetSymbolAddress((void**)&WH, g_wh);
    cudaGetSymbolAddress((void**)&WL, g_wl);

    const int xn4 = MTOT * DMODEL / 4;

    rope_table_kernel<<<(SEQ*(HDIM/2) + 255)/256, 256>>>();                 // #1
    split4w_kernel<<<(4*(WSZ/4) + 255)/256, 256>>>(wq, wk, wv, wo);         // #2
    split_kernel<<<(xn4 + 255)/256, 256>>>(x, XH, XL, xn4);                 // #3

    dim3 gblk(256);
    dim3 ggrid(DMODEL/128, MTOT/128);   // (6, 64)

    gemm_mma_kernel<1><<<ggrid, gblk>>>(XH, XL, WH,         WL,         Q); // #4
    gemm_mma_kernel<2><<<ggrid, gblk>>>(XH, XL, WH + WSZ,   WL + WSZ,   K); // #5
    gemm_mma_kernel<0><<<ggrid, gblk>>>(XH, XL, WH + 2*WSZ, WL + 2*WSZ, V); // #6 (ncu)

    attn_kernel<<<dim3(SEQ/256, BATCH*NHEADS), 128>>>();                    // #7

    split_kernel<<<(xn4 + 255)/256, 256>>>(AO, XH, XL, xn4);                // #8
    gemm_mma_kernel<0><<<ggrid, gblk>>>(XH, XL, WH + 3*WSZ, WL + 3*WSZ, out); // #9
}

// round 7
// speedup vs baseline: 4.2199x; 2.2291x over previous
#include <cuda_runtime.h>
#include <cuda_bf16.h>
#include <math.h>
#include <cstdint>

#define BATCH   4
#define SEQ     2048
#define DMODEL  768
#define NHEADS  12
#define HDIM    64
#define MTOT    (BATCH*SEQ)   /* 8192 */
#define WSZ     (DMODEL*DMODEL)

// Scratch (static device arrays: allocation-free per harness rules)
__device__ float2 g_tbl[SEQ*(HDIM/2)];
__device__ __nv_bfloat16 g_xh[MTOT*DMODEL], g_xl[MTOT*DMODEL];   // x / AO splits
__device__ __nv_bfloat16 g_wh[4*WSZ],       g_wl[4*WSZ];
__device__ __nv_bfloat16 g_Qh[MTOT*DMODEL], g_Ql[MTOT*DMODEL];
__device__ __nv_bfloat16 g_Kh[MTOT*DMODEL], g_Kl[MTOT*DMODEL];
__device__ __nv_bfloat16 g_Vh[MTOT*DMODEL], g_Vl[MTOT*DMODEL];
__device__ __nv_bfloat16 g_AOh[MTOT*DMODEL], g_AOl[MTOT*DMODEL];

// ===========================================================================
// Helpers
// ===========================================================================
__device__ __forceinline__ uint32_t smem_u32(const void* p) {
    uint32_t a;
    asm("{ .reg .u64 t; cvta.to.shared.u64 t, %1; cvt.u32.u64 %0, t; }" : "=r"(a) : "l"(p));
    return a;
}
__device__ __forceinline__ void ldsm4(uint32_t* r, uint32_t addr) {
    asm volatile("ldmatrix.sync.aligned.m8n8.x4.shared.b16 {%0,%1,%2,%3}, [%4];"
        : "=r"(r[0]), "=r"(r[1]), "=r"(r[2]), "=r"(r[3]) : "r"(addr));
}
__device__ __forceinline__ void ldsm4t(uint32_t* r, uint32_t addr) {
    asm volatile("ldmatrix.sync.aligned.m8n8.x4.trans.shared.b16 {%0,%1,%2,%3}, [%4];"
        : "=r"(r[0]), "=r"(r[1]), "=r"(r[2]), "=r"(r[3]) : "r"(addr));
}
__device__ __forceinline__ void mma16816(float* c, const uint32_t* a, uint32_t b0, uint32_t b1) {
    asm volatile("mma.sync.aligned.m16n8k16.row.col.f32.bf16.bf16.f32 "
        "{%0,%1,%2,%3}, {%4,%5,%6,%7}, {%8,%9}, {%0,%1,%2,%3};"
        : "+f"(c[0]), "+f"(c[1]), "+f"(c[2]), "+f"(c[3])
        : "r"(a[0]), "r"(a[1]), "r"(a[2]), "r"(a[3]), "r"(b0), "r"(b1));
}
__device__ __forceinline__ uint32_t pack2(float x, float y) {
    __nv_bfloat16 hx = __float2bfloat16(x), hy = __float2bfloat16(y);
    return (uint32_t)__bfloat16_as_ushort(hx) | ((uint32_t)__bfloat16_as_ushort(hy) << 16);
}
__device__ __forceinline__ void split2(float x, float y, uint32_t& hi, uint32_t& lo) {
    __nv_bfloat16 hx = __float2bfloat16(x), hy = __float2bfloat16(y);
    hi = (uint32_t)__bfloat16_as_ushort(hx) | ((uint32_t)__bfloat16_as_ushort(hy) << 16);
    lo = pack2(x - __bfloat162float(hx), y - __bfloat162float(hy));
}

// ---------------------------------------------------------------------------
// RoPE table (fp64-accurate sincos, 65536 entries)
// ---------------------------------------------------------------------------
__global__ void rope_table_kernel()
{
    int idx = blockIdx.x * blockDim.x + threadIdx.x;
    if (idx >= SEQ * (HDIM/2)) return;
    int s = idx >> 5, j = idx & 31;
    float invf = (float)pow(10000.0, -(double)(2*j) / (double)HDIM);
    float angf = (float)s * invf;
    double sn, cs;
    sincos((double)angf, &sn, &cs);
    g_tbl[idx] = make_float2((float)cs, (float)sn);
}

// ---------------------------------------------------------------------------
// One kernel splits x AND all 4 weights into hi/lo bf16 (bandwidth-bound)
// ---------------------------------------------------------------------------
__device__ __forceinline__ void split4v(float4 v, uint2& hi, uint2& lo)
{
    split2(v.x, v.y, hi.x, lo.x);
    split2(v.z, v.w, hi.y, lo.y);
}

__global__ void splits_all_kernel(const float* __restrict__ x,
                                  const float* __restrict__ w0, const float* __restrict__ w1,
                                  const float* __restrict__ w2, const float* __restrict__ w3)
{
    const int xn4 = MTOT * DMODEL / 4;
    const int wn4 = WSZ / 4;
    int i = blockIdx.x * blockDim.x + threadIdx.x;
    uint2 h, l;
    if (i < xn4) {
        split4v(((const float4*)x)[i], h, l);
        ((uint2*)g_xh)[i] = h;
        ((uint2*)g_xl)[i] = l;
    } else {
        int j = i - xn4;
        if (j >= 4 * wn4) return;
        int ws = j / wn4, off = j - ws * wn4;
        const float* src = (ws == 0) ? w0 : (ws == 1) ? w1 : (ws == 2) ? w2 : w3;
        split4v(((const float4*)src)[off], h, l);
        ((uint2*)g_wh)[j] = h;
        ((uint2*)g_wl)[j] = l;
    }
}

// ===========================================================================
// Split-bf16 tensor-core GEMM: C = A @ W^T (both K-contiguous).
// CTA 128x128, 8 warps, warp 64x32. ROPE: 0/1(Q,+0.125)/2(K).
// OSPLIT: 0 -> fp32 C; 1 -> bf16 hi/lo split outputs Ch/Cl.
// ===========================================================================
#define SROW 80

template<int ROPE, int OSPLIT>
__global__ __launch_bounds__(256) void gemm_mma_kernel(
    const __nv_bfloat16* __restrict__ Ah, const __nv_bfloat16* __restrict__ Al,
    const __nv_bfloat16* __restrict__ Bh, const __nv_bfloat16* __restrict__ Bl,
    float* __restrict__ C, __nv_bfloat16* __restrict__ Ch, __nv_bfloat16* __restrict__ Cl)
{
    __shared__ __align__(16) char sm[4 * 128 * SROW];
    const uint32_t sAH = smem_u32(sm);
    const uint32_t sAL = sAH + 128 * SROW;
    const uint32_t sBH = sAL + 128 * SROW;
    const uint32_t sBL = sBH + 128 * SROW;

    const int tid  = threadIdx.x;
    const int wid  = tid >> 5, lane = tid & 31;
    const int wm   = wid >> 2, wn = wid & 3;
    const int m0   = blockIdx.y * 128;
    const int n0   = blockIdx.x * 128;

    const int r  = tid >> 1;
    const int chh = (tid & 1) * 16;
    const __nv_bfloat16* gAh = Ah + (size_t)(m0 + r) * DMODEL + chh;
    const __nv_bfloat16* gAl = Al + (size_t)(m0 + r) * DMODEL + chh;
    const __nv_bfloat16* gBh = Bh + (size_t)(n0 + r) * DMODEL + chh;
    const __nv_bfloat16* gBl = Bl + (size_t)(n0 + r) * DMODEL + chh;
    const uint32_t soff = (uint32_t)(r * SROW + chh * 2);

    float acc[4][4][4] = {};

    const uint32_t a_row  = wm * 64 + (lane & 15);
    const uint32_t a_colb = (lane >> 4) * 16;
    const uint32_t b_row  = wn * 32 + (lane & 7) + ((lane >> 4) << 3);
    const uint32_t b_colb = ((lane >> 3) & 1) * 16;

    for (int kc = 0; kc < DMODEL; kc += 32) {
        __syncthreads();
        *(uint4*)(sm + (sAH - smem_u32(sm)) + soff)      = *(const uint4*)(gAh + kc);
        *(uint4*)(sm + (sAH - smem_u32(sm)) + soff + 16) = *(const uint4*)(gAh + kc + 8);
        *(uint4*)(sm + (sAL - smem_u32(sm)) + soff)      = *(const uint4*)(gAl + kc);
        *(uint4*)(sm + (sAL - smem_u32(sm)) + soff + 16) = *(const uint4*)(gAl + kc + 8);
        *(uint4*)(sm + (sBH - smem_u32(sm)) + soff)      = *(const uint4*)(gBh + kc);
        *(uint4*)(sm + (sBH - smem_u32(sm)) + soff + 16) = *(const uint4*)(gBh + kc + 8);
        *(uint4*)(sm + (sBL - smem_u32(sm)) + soff)      = *(const uint4*)(gBl + kc);
        *(uint4*)(sm + (sBL - smem_u32(sm)) + soff + 16) = *(const uint4*)(gBl + kc + 8);
        __syncthreads();

        #pragma unroll
        for (int ks = 0; ks < 2; ks++) {
            const uint32_t kb = ks * 32;
            #pragma unroll
            for (int pass = 0; pass < 3; pass++) {
                const uint32_t aBase = (pass == 2) ? sAL : sAH;
                const uint32_t bBase = (pass == 1) ? sBL : sBH;
                uint32_t afr[4][4];
                #pragma unroll
                for (int mf = 0; mf < 4; mf++)
                    ldsm4(afr[mf], aBase + (a_row + mf*16) * SROW + kb + a_colb);
                uint32_t bfr[2][4];
                #pragma unroll
                for (int nh = 0; nh < 2; nh++)
                    ldsm4(bfr[nh], bBase + (b_row + nh*16) * SROW + kb + b_colb);
                #pragma unroll
                for (int mf = 0; mf < 4; mf++) {
                    #pragma unroll
                    for (int nh = 0; nh < 2; nh++) {
                        mma16816(acc[mf][2*nh],   afr[mf], bfr[nh][0], bfr[nh][1]);
                        mma16816(acc[mf][2*nh+1], afr[mf], bfr[nh][2], bfr[nh][3]);
                    }
                }
            }
        }
    }

    const int lrow = lane >> 2;
    const int lcol = (lane & 3) * 2;
    #pragma unroll
    for (int mf = 0; mf < 4; mf++) {
        #pragma unroll
        for (int nf = 0; nf < 4; nf++) {
            float* c = acc[mf][nf];
            const int col = n0 + wn*32 + nf*8 + lcol;
            #pragma unroll
            for (int half = 0; half < 2; half++) {
                const int m = m0 + wm*64 + mf*16 + lrow + half*8;
                float v1 = c[half*2], v2 = c[half*2+1];
                if (ROPE != 0) {
                    const int s = m & (SEQ - 1);
                    float2 cs = g_tbl[s * (HDIM/2) + ((col & (HDIM-1)) >> 1)];
                    float r1 = v1*cs.x - v2*cs.y;
                    float r2 = v1*cs.y + v2*cs.x;
                    if (ROPE == 1) { r1 *= 0.125f; r2 *= 0.125f; }
                    v1 = r1; v2 = r2;
                }
                if (OSPLIT) {
                    uint32_t hi, lo;
                    split2(v1, v2, hi, lo);
                    *(uint32_t*)&Ch[(size_t)m * DMODEL + col] = hi;
                    *(uint32_t*)&Cl[(size_t)m * DMODEL + col] = lo;
                } else {
                    *(float2*)&C[(size_t)m * DMODEL + col] = make_float2(v1, v2);
                }
            }
        }
    }
}

// ===========================================================================
// Tensor-core causal flash attention, split-bf16.
// CTA: 128 threads (4 warps), Br=64 q rows (16/warp), Bc=64.
// Strips paired bx <-> 31-bx (uniform 34 k-tiles). Writes AO hi/lo splits.
// ===========================================================================
#define ASROW 144   /* bytes per 64-col bf16 smem row (+8 pad) */

__global__ __launch_bounds__(128) void attn_mma_kernel()
{
    __shared__ __align__(16) char sm[4 * 64 * ASROW];   // Kh | Kl | Vh | Vl
    const uint32_t sKh = smem_u32(sm);
    const uint32_t sKl = sKh + 64 * ASROW;
    const uint32_t sVh = sKl + 64 * ASROW;
    const uint32_t sVl = sVh + 64 * ASROW;

    const int tid  = threadIdx.x;
    const int wid  = tid >> 5, lane = tid & 31;
    const int bh   = blockIdx.y;
    const int b    = bh / NHEADS, h = bh % NHEADS;
    const size_t rowbase = (size_t)(b * SEQ);
    const int hc = h * HDIM;

    const int ldr = tid >> 1;            // loader row 0..63
    const int ldc = (tid & 1) * 32;      // loader col 0 or 32

    const uint32_t a_row  = (lane & 15);
    const uint32_t a_colb = (lane >> 4) * 16;
    const uint32_t b_row  = (lane & 7) + ((lane >> 4) << 3);
    const uint32_t b_colb = ((lane >> 3) & 1) * 16;
    const uint32_t v_krow  = (lane & 7) + (((lane >> 3) & 1) << 3);
    const uint32_t v_ncolb = (lane >> 4) * 16;

    for (int sidx = 0; sidx < 2; sidx++) {
        const int bx = (sidx == 0) ? (int)blockIdx.x : (31 - (int)blockIdx.x);
        const int q0 = bx * 64;
        const int nk = bx + 1;

        // ---- stage Q (hi then lo) through sKh, keep fragments in registers ----
        uint32_t qh[4][4], ql[4][4];
        {
            const __nv_bfloat16* src = &g_Qh[(rowbase + q0 + ldr) * DMODEL + hc + ldc];
            #pragma unroll
            for (int i = 0; i < 4; i++)
                *(uint4*)(sm + ldr * ASROW + ldc * 2 + i * 16) = *(const uint4*)(src + i * 8);
            __syncthreads();
            #pragma unroll
            for (int kk = 0; kk < 4; kk++)
                ldsm4(qh[kk], sKh + (wid * 16 + a_row) * ASROW + kk * 32 + a_colb);
            __syncthreads();
            const __nv_bfloat16* src2 = &g_Ql[(rowbase + q0 + ldr) * DMODEL + hc + ldc];
            #pragma unroll
            for (int i = 0; i < 4; i++)
                *(uint4*)(sm + ldr * ASROW + ldc * 2 + i * 16) = *(const uint4*)(src2 + i * 8);
            __syncthreads();
            #pragma unroll
            for (int kk = 0; kk < 4; kk++)
                ldsm4(ql[kk], sKh + (wid * 16 + a_row) * ASROW + kk * 32 + a_colb);
            __syncthreads();
        }

        float o[8][4];
        #pragma unroll
        for (int j = 0; j < 8; j++)
            #pragma unroll
            for (int i = 0; i < 4; i++) o[j][i] = 0.f;
        float m0h = -INFINITY, m1h = -INFINITY, l0 = 0.f, l1 = 0.f;

        for (int kt = 0; kt < nk; kt++) {
            const int kb = kt * 64;
            {
                const size_t srow = (rowbase + kb + ldr) * DMODEL + hc + ldc;
                const uint32_t doff = ldr * ASROW + ldc * 2;
                #pragma unroll
                for (int i = 0; i < 4; i++) {
                    *(uint4*)(sm + 0*64*ASROW + doff + i*16) = *(const uint4*)(&g_Kh[srow] + i*8);
                    *(uint4*)(sm + 1*64*ASROW + doff + i*16) = *(const uint4*)(&g_Kl[srow] + i*8);
                    *(uint4*)(sm + 2*64*ASROW + doff + i*16) = *(const uint4*)(&g_Vh[srow] + i*8);
                    *(uint4*)(sm + 3*64*ASROW + doff + i*16) = *(const uint4*)(&g_Vl[srow] + i*8);
                }
            }
            __syncthreads();

            // ---- S = Q @ K^T (3 split passes) ----
            float sc[8][4];
            #pragma unroll
            for (int j = 0; j < 8; j++)
                #pragma unroll
                for (int i = 0; i < 4; i++) sc[j][i] = 0.f;

            #pragma unroll
            for (int pass = 0; pass < 3; pass++) {
                const uint32_t (*qf)[4] = (pass == 2) ? ql : qh;
                const uint32_t kbase = (pass == 1) ? sKl : sKh;
                #pragma unroll
                for (int kk = 0; kk < 4; kk++) {
                    uint32_t bf[4][4];
                    #pragma unroll
                    for (int nt = 0; nt < 4; nt++)
                        ldsm4(bf[nt], kbase + (nt*16 + b_row) * ASROW + kk*32 + b_colb);
                    #pragma unroll
                    for (int nt = 0; nt < 4; nt++) {
                        mma16816(sc[2*nt],   qf[kk], bf[nt][0], bf[nt][1]);
                        mma16816(sc[2*nt+1], qf[kk], bf[nt][2], bf[nt][3]);
                    }
                }
            }

            // ---- causal mask (diagonal tile only) ----
            const int r0 = q0 + wid*16 + (lane >> 2);
            const int r1 = r0 + 8;
            if (kt == nk - 1) {
                #pragma unroll
                for (int j = 0; j < 8; j++) {
                    const int c0 = kb + j*8 + (lane & 3)*2;
                    if (c0     > r0) sc[j][0] = -1e30f;
                    if (c0 + 1 > r0) sc[j][1] = -1e30f;
                    if (c0     > r1) sc[j][2] = -1e30f;
                    if (c0 + 1 > r1) sc[j][3] = -1e30f;
                }
            }

            // ---- online softmax ----
            float mx0 = -INFINITY, mx1 = -INFINITY;
            #pragma unroll
            for (int j = 0; j < 8; j++) {
                mx0 = fmaxf(mx0, fmaxf(sc[j][0], sc[j][1]));
                mx1 = fmaxf(mx1, fmaxf(sc[j][2], sc[j][3]));
            }
            mx0 = fmaxf(mx0, __shfl_xor_sync(0xffffffffu, mx0, 1));
            mx0 = fmaxf(mx0, __shfl_xor_sync(0xffffffffu, mx0, 2));
            mx1 = fmaxf(mx1, __shfl_xor_sync(0xffffffffu, mx1, 1));
            mx1 = fmaxf(mx1, __shfl_xor_sync(0xffffffffu, mx1, 2));
            const float nm0 = fmaxf(m0h, mx0), nm1 = fmaxf(m1h, mx1);
            const float cr0 = __expf(m0h - nm0), cr1 = __expf(m1h - nm1);
            m0h = nm0; m1h = nm1;
            l0 *= cr0; l1 *= cr1;
            #pragma unroll
            for (int j = 0; j < 8; j++) {
                o[j][0] *= cr0; o[j][1] *= cr0;
                o[j][2] *= cr1; o[j][3] *= cr1;
            }
            #pragma unroll
            for (int j = 0; j < 8; j++) {
                sc[j][0] = __expf(sc[j][0] - nm0);
                sc[j][1] = __expf(sc[j][1] - nm0);
                sc[j][2] = __expf(sc[j][2] - nm1);
                sc[j][3] = __expf(sc[j][3] - nm1);
                l0 += sc[j][0] + sc[j][1];
                l1 += sc[j][2] + sc[j][3];
            }

            // ---- pack P (hi/lo) into A-fragments ----
            uint32_t ph[4][4], pl[4][4];
            #pragma unroll
            for (int ks = 0; ks < 4; ks++) {
                split2(sc[2*ks][0],   sc[2*ks][1],   ph[ks][0], pl[ks][0]);
                split2(sc[2*ks][2],   sc[2*ks][3],   ph[ks][1], pl[ks][1]);
                split2(sc[2*ks+1][0], sc[2*ks+1][1], ph[ks][2], pl[ks][2]);
                split2(sc[2*ks+1][2], sc[2*ks+1][3], ph[ks][3], pl[ks][3]);
            }

            // ---- O += P @ V (3 split passes) ----
            #pragma unroll
            for (int pass = 0; pass < 3; pass++) {
                const uint32_t (*pf)[4] = (pass == 2) ? pl : ph;
                const uint32_t vbase = (pass == 1) ? sVl : sVh;
                #pragma unroll
                for (int ks = 0; ks < 4; ks++) {
                    #pragma unroll
                    for (int nt = 0; nt < 4; nt++) {
                        uint32_t vf[4];
                        ldsm4t(vf, vbase + (ks*16 + v_krow) * ASROW + nt*32 + v_ncolb);
                        mma16816(o[2*nt],   pf[ks], vf[0], vf[1]);
                        mma16816(o[2*nt+1], pf[ks], vf[2], vf[3]);
                    }
                }
            }
            __syncthreads();
        }

        // ---- finalize & write AO splits ----
        l0 += __shfl_xor_sync(0xffffffffu, l0, 1);
        l0 += __shfl_xor_sync(0xffffffffu, l0, 2);
        l1 += __shfl_xor_sync(0xffffffffu, l1, 1);
        l1 += __shfl_xor_sync(0xffffffffu, l1, 2);
        const float inv0 = 1.f / l0, inv1 = 1.f / l1;
        const size_t row0 = rowbase + q0 + wid*16 + (lane >> 2);
        const size_t row1 = row0 + 8;
        #pragma unroll
        for (int j = 0; j < 8; j++) {
            const int col = hc + j*8 + (lane & 3)*2;
            uint32_t hi, lo;
            split2(o[j][0]*inv0, o[j][1]*inv0, hi, lo);
            *(uint32_t*)&g_AOh[row0 * DMODEL + col] = hi;
            *(uint32_t*)&g_AOl[row0 * DMODEL + col] = lo;
            split2(o[j][2]*inv1, o[j][3]*inv1, hi, lo);
            *(uint32_t*)&g_AOh[row1 * DMODEL + col] = hi;
            *(uint32_t*)&g_AOl[row1 * DMODEL + col] = lo;
        }
        __syncthreads();
    }
}

// ---------------------------------------------------------------------------
extern "C" void kernel_launch(void* const* d_in, const int* in_sizes, int n_in,
                              void* d_out, int out_size)
{
    const float* x  = (const float*)d_in[0];
    const float* wq = (const float*)d_in[1];
    const float* wk = (const float*)d_in[2];
    const float* wv = (const float*)d_in[3];
    const float* wo = (const float*)d_in[4];
    float* out = (float*)d_out;

    __nv_bfloat16 *XH, *XL, *WH, *WL, *QH, *QL, *KH, *KL, *VH, *VL, *AH, *AL;
    cudaGetSymbolAddress((void**)&XH, g_xh);  cudaGetSymbolAddress((void**)&XL, g_xl);
    cudaGetSymbolAddress((void**)&WH, g_wh);  cudaGetSymbolAddress((void**)&WL, g_wl);
    cudaGetSymbolAddress((void**)&QH, g_Qh);  cudaGetSymbolAddress((void**)&QL, g_Ql);
    cudaGetSymbolAddress((void**)&KH, g_Kh);  cudaGetSymbolAddress((void**)&KL, g_Kl);
    cudaGetSymbolAddress((void**)&VH, g_Vh);  cudaGetSymbolAddress((void**)&VL, g_Vl);
    cudaGetSymbolAddress((void**)&AH, g_AOh); cudaGetSymbolAddress((void**)&AL, g_AOl);

    const int xn4 = MTOT * DMODEL / 4;
    const int tot4 = xn4 + 4 * (WSZ / 4);

    rope_table_kernel<<<(SEQ*(HDIM/2) + 255)/256, 256>>>();                  // #1
    splits_all_kernel<<<(tot4 + 255)/256, 256>>>(x, wq, wk, wv, wo);         // #2

    dim3 gblk(256);
    dim3 ggrid(DMODEL/128, MTOT/128);   // (6, 64)

    gemm_mma_kernel<1,1><<<ggrid, gblk>>>(XH, XL, WH,       WL,       nullptr, QH, QL); // #3
    gemm_mma_kernel<2,1><<<ggrid, gblk>>>(XH, XL, WH+WSZ,   WL+WSZ,   nullptr, KH, KL); // #4
    gemm_mma_kernel<0,1><<<ggrid, gblk>>>(XH, XL, WH+2*WSZ, WL+2*WSZ, nullptr, VH, VL); // #5

    attn_mma_kernel<<<dim3(16, BATCH*NHEADS), 128>>>();                      // #6 (ncu)

    gemm_mma_kernel<0,0><<<ggrid, gblk>>>(AH, AL, WH+3*WSZ, WL+3*WSZ, out, nullptr, nullptr); // #7
}

// round 8
// speedup vs baseline: 4.5627x; 1.0812x over previous
#include <cuda_runtime.h>
#include <cuda_bf16.h>
#include <math.h>
#include <cstdint>

#define BATCH   4
#define SEQ     2048
#define DMODEL  768
#define NHEADS  12
#define HDIM    64
#define MTOT    (BATCH*SEQ)   /* 8192 */
#define WSZ     (DMODEL*DMODEL)

// Scratch (static device arrays: allocation-free per harness rules)
__device__ float2 g_tbl[SEQ*(HDIM/2)];
__device__ __nv_bfloat16 g_xh[MTOT*DMODEL], g_xl[MTOT*DMODEL];
__device__ __nv_bfloat16 g_wh[4*WSZ],       g_wl[4*WSZ];
__device__ __nv_bfloat16 g_Qh[MTOT*DMODEL], g_Ql[MTOT*DMODEL];
__device__ __nv_bfloat16 g_Kh[MTOT*DMODEL], g_Kl[MTOT*DMODEL];
__device__ __nv_bfloat16 g_Vh[MTOT*DMODEL], g_Vl[MTOT*DMODEL];
__device__ __nv_bfloat16 g_AOh[MTOT*DMODEL], g_AOl[MTOT*DMODEL];

// ===========================================================================
// Helpers
// ===========================================================================
__device__ __forceinline__ uint32_t smem_u32(const void* p) {
    uint32_t a;
    asm("{ .reg .u64 t; cvta.to.shared.u64 t, %1; cvt.u32.u64 %0, t; }" : "=r"(a) : "l"(p));
    return a;
}
__device__ __forceinline__ void ldsm4(uint32_t* r, uint32_t addr) {
    asm volatile("ldmatrix.sync.aligned.m8n8.x4.shared.b16 {%0,%1,%2,%3}, [%4];"
        : "=r"(r[0]), "=r"(r[1]), "=r"(r[2]), "=r"(r[3]) : "r"(addr));
}
__device__ __forceinline__ void ldsm4t(uint32_t* r, uint32_t addr) {
    asm volatile("ldmatrix.sync.aligned.m8n8.x4.trans.shared.b16 {%0,%1,%2,%3}, [%4];"
        : "=r"(r[0]), "=r"(r[1]), "=r"(r[2]), "=r"(r[3]) : "r"(addr));
}
__device__ __forceinline__ void mma16816(float* c, const uint32_t* a, uint32_t b0, uint32_t b1) {
    asm volatile("mma.sync.aligned.m16n8k16.row.col.f32.bf16.bf16.f32 "
        "{%0,%1,%2,%3}, {%4,%5,%6,%7}, {%8,%9}, {%0,%1,%2,%3};"
        : "+f"(c[0]), "+f"(c[1]), "+f"(c[2]), "+f"(c[3])
        : "r"(a[0]), "r"(a[1]), "r"(a[2]), "r"(a[3]), "r"(b0), "r"(b1));
}
__device__ __forceinline__ uint32_t pack2(float x, float y) {
    __nv_bfloat16 hx = __float2bfloat16(x), hy = __float2bfloat16(y);
    return (uint32_t)__bfloat16_as_ushort(hx) | ((uint32_t)__bfloat16_as_ushort(hy) << 16);
}
__device__ __forceinline__ void split2(float x, float y, uint32_t& hi, uint32_t& lo) {
    __nv_bfloat16 hx = __float2bfloat16(x), hy = __float2bfloat16(y);
    hi = (uint32_t)__bfloat16_as_ushort(hx) | ((uint32_t)__bfloat16_as_ushort(hy) << 16);
    lo = pack2(x - __bfloat162float(hx), y - __bfloat162float(hy));
}
__device__ __forceinline__ void cp16(uint32_t dst, const void* src) {
    asm volatile("cp.async.cg.shared.global [%0], [%1], 16;" :: "r"(dst), "l"(src) : "memory");
}
#define CP_COMMIT() asm volatile("cp.async.commit_group;" ::: "memory")
#define CP_WAIT(n)  asm volatile("cp.async.wait_group %0;" :: "n"(n) : "memory")

// ---------------------------------------------------------------------------
// RoPE table (fp64-accurate sincos; 3 launches for ncu launch-count padding)
// ---------------------------------------------------------------------------
__global__ void rope_table_kernel(int s_base, int s_cnt)
{
    int idx = blockIdx.x * blockDim.x + threadIdx.x;
    if (idx >= s_cnt * (HDIM/2)) return;
    int s = s_base + (idx >> 5), j = idx & 31;
    float invf = (float)pow(10000.0, -(double)(2*j) / (double)HDIM);
    float angf = (float)s * invf;
    double sn, cs;
    sincos((double)angf, &sn, &cs);
    g_tbl[s * (HDIM/2) + j] = make_float2((float)cs, (float)sn);
}

// ---------------------------------------------------------------------------
// hi/lo bf16 splits
// ---------------------------------------------------------------------------
__device__ __forceinline__ void split4v(float4 v, uint2& hi, uint2& lo)
{
    split2(v.x, v.y, hi.x, lo.x);
    split2(v.z, v.w, hi.y, lo.y);
}
__global__ void splitw_kernel(const float* __restrict__ w0, const float* __restrict__ w1,
                              const float* __restrict__ w2, const float* __restrict__ w3)
{
    const int wn4 = WSZ / 4;
    int i = blockIdx.x * blockDim.x + threadIdx.x;
    if (i >= 4 * wn4) return;
    int ws = i / wn4, off = i - ws * wn4;
    const float* src = (ws == 0) ? w0 : (ws == 1) ? w1 : (ws == 2) ? w2 : w3;
    uint2 h, l;
    split4v(((const float4*)src)[off], h, l);
    ((uint2*)g_wh)[i] = h;
    ((uint2*)g_wl)[i] = l;
}
__global__ void splitx_kernel(const float* __restrict__ x)
{
    const int xn4 = MTOT * DMODEL / 4;
    int i = blockIdx.x * blockDim.x + threadIdx.x;
    if (i >= xn4) return;
    uint2 h, l;
    split4v(((const float4*)x)[i], h, l);
    ((uint2*)g_xh)[i] = h;
    ((uint2*)g_xl)[i] = l;
}

// ===========================================================================
// Double-buffered split-bf16 tensor-core GEMM (cp.async pipeline).
// FUSED=1: QKV in one launch, grid (18,64); section = blockIdx.x/6 picks
//          weight slice + rope mode + split outputs.
// FUSED=0: single GEMM (WO), fp32 output C.
// CTA tile 128x128, 8 warps, warp 64x32, K chunks of 32, 2 smem stages.
// ===========================================================================
#define SROW     80
#define BUF_SZ   (128*SROW)        /* one operand buffer  */
#define STAGE_SZ (4*BUF_SZ)        /* AH AL BH BL         */
#define NCHUNK   (DMODEL/32)       /* 24                  */

__device__ __forceinline__ void stage_load(uint32_t base, uint32_t soff,
    const __nv_bfloat16* pAh, const __nv_bfloat16* pAl,
    const __nv_bfloat16* pBh, const __nv_bfloat16* pBl)
{
    cp16(base + 0*BUF_SZ + soff,      pAh);
    cp16(base + 0*BUF_SZ + soff + 16, pAh + 8);
    cp16(base + 1*BUF_SZ + soff,      pAl);
    cp16(base + 1*BUF_SZ + soff + 16, pAl + 8);
    cp16(base + 2*BUF_SZ + soff,      pBh);
    cp16(base + 2*BUF_SZ + soff + 16, pBh + 8);
    cp16(base + 3*BUF_SZ + soff,      pBl);
    cp16(base + 3*BUF_SZ + soff + 16, pBl + 8);
}

template<int FUSED>
__global__ __launch_bounds__(256) void gemm_db_kernel(
    const __nv_bfloat16* __restrict__ Ah, const __nv_bfloat16* __restrict__ Al,
    const __nv_bfloat16* __restrict__ Bh0, const __nv_bfloat16* __restrict__ Bl0,
    __nv_bfloat16* __restrict__ QH, __nv_bfloat16* __restrict__ QL,
    __nv_bfloat16* __restrict__ KH, __nv_bfloat16* __restrict__ KL,
    __nv_bfloat16* __restrict__ VH, __nv_bfloat16* __restrict__ VL,
    float* __restrict__ C)
{
    extern __shared__ __align__(16) char sm[];
    const uint32_t sb = smem_u32(sm);

    const int tid = threadIdx.x;
    const int wid = tid >> 5, lane = tid & 31;
    const int wm  = wid >> 2, wn = wid & 3;
    const int m0  = blockIdx.y * 128;

    int sec, nx;
    if (FUSED) { sec = blockIdx.x / 6; nx = blockIdx.x % 6; }
    else       { sec = 0;              nx = blockIdx.x;     }
    const int n0 = nx * 128;
    const __nv_bfloat16* Bh = Bh0 + (size_t)sec * WSZ;
    const __nv_bfloat16* Bl = Bl0 + (size_t)sec * WSZ;

    const int r   = tid >> 1;
    const int chh = (tid & 1) * 16;
    const size_t aoff = (size_t)(m0 + r) * DMODEL + chh;
    const size_t boff = (size_t)(n0 + r) * DMODEL + chh;
    const uint32_t soff = (uint32_t)(r * SROW + chh * 2);

    const uint32_t a_row  = wm * 64 + (lane & 15);
    const uint32_t a_colb = (lane >> 4) * 16;
    const uint32_t b_row  = wn * 32 + (lane & 7) + ((lane >> 4) << 3);
    const uint32_t b_colb = ((lane >> 3) & 1) * 16;

    float acc[4][4][4] = {};

    // prologue: stage 0 <- chunk 0
    stage_load(sb, soff, Ah + aoff, Al + aoff, Bh + boff, Bl + boff);
    CP_COMMIT();

    for (int c = 0; c < NCHUNK; c++) {
        const uint32_t stb = sb + (uint32_t)(c & 1) * STAGE_SZ;
        if (c + 1 < NCHUNK) {
            const int kc = (c + 1) * 32;
            stage_load(sb + (uint32_t)((c + 1) & 1) * STAGE_SZ, soff,
                       Ah + aoff + kc, Al + aoff + kc, Bh + boff + kc, Bl + boff + kc);
            CP_COMMIT();
            CP_WAIT(1);
        } else {
            CP_WAIT(0);
        }
        __syncthreads();

        #pragma unroll
        for (int ks = 0; ks < 2; ks++) {
            const uint32_t kb = ks * 32;
            #pragma unroll
            for (int pass = 0; pass < 3; pass++) {
                const uint32_t aBase = stb + ((pass == 2) ? BUF_SZ : 0);
                const uint32_t bBase = stb + 2*BUF_SZ + ((pass == 1) ? BUF_SZ : 0);
                uint32_t afr[4][4];
                #pragma unroll
                for (int mf = 0; mf < 4; mf++)
                    ldsm4(afr[mf], aBase + (a_row + mf*16) * SROW + kb + a_colb);
                uint32_t bfr[2][4];
                #pragma unroll
                for (int nh = 0; nh < 2; nh++)
                    ldsm4(bfr[nh], bBase + (b_row + nh*16) * SROW + kb + b_colb);
                #pragma unroll
                for (int mf = 0; mf < 4; mf++) {
                    #pragma unroll
                    for (int nh = 0; nh < 2; nh++) {
                        mma16816(acc[mf][2*nh],   afr[mf], bfr[nh][0], bfr[nh][1]);
                        mma16816(acc[mf][2*nh+1], afr[mf], bfr[nh][2], bfr[nh][3]);
                    }
                }
            }
        }
        __syncthreads();
    }

    // Epilogue
    const int lrow = lane >> 2;
    const int lcol = (lane & 3) * 2;
    const int ropeMode = FUSED ? ((sec == 0) ? 1 : (sec == 1) ? 2 : 0) : 0;
    __nv_bfloat16 *Ch = nullptr, *Cl = nullptr;
    if (FUSED) {
        Ch = (sec == 0) ? QH : (sec == 1) ? KH : VH;
        Cl = (sec == 0) ? QL : (sec == 1) ? KL : VL;
    }
    #pragma unroll
    for (int mf = 0; mf < 4; mf++) {
        #pragma unroll
        for (int nf = 0; nf < 4; nf++) {
            float* cc = acc[mf][nf];
            const int col = n0 + wn*32 + nf*8 + lcol;
            #pragma unroll
            for (int half = 0; half < 2; half++) {
                const int m = m0 + wm*64 + mf*16 + lrow + half*8;
                float v1 = cc[half*2], v2 = cc[half*2+1];
                if (ropeMode != 0) {
                    const int s = m & (SEQ - 1);
                    float2 cs = g_tbl[s * (HDIM/2) + ((col & (HDIM-1)) >> 1)];
                    float r1 = v1*cs.x - v2*cs.y;
                    float r2 = v1*cs.y + v2*cs.x;
                    if (ropeMode == 1) { r1 *= 0.125f; r2 *= 0.125f; }
                    v1 = r1; v2 = r2;
                }
                if (FUSED) {
                    uint32_t hi, lo;
                    split2(v1, v2, hi, lo);
                    *(uint32_t*)&Ch[(size_t)m * DMODEL + col] = hi;
                    *(uint32_t*)&Cl[(size_t)m * DMODEL + col] = lo;
                } else {
                    *(float2*)&C[(size_t)m * DMODEL + col] = make_float2(v1, v2);
                }
            }
        }
    }
}

// ===========================================================================
// Tensor-core causal flash attention, split-bf16 (unchanged from round 7).
// ===========================================================================
#define ASROW 144

__global__ __launch_bounds__(128) void attn_mma_kernel()
{
    __shared__ __align__(16) char sm[4 * 64 * ASROW];
    const uint32_t sKh = smem_u32(sm);
    const uint32_t sKl = sKh + 64 * ASROW;
    const uint32_t sVh = sKl + 64 * ASROW;
    const uint32_t sVl = sVh + 64 * ASROW;

    const int tid  = threadIdx.x;
    const int wid  = tid >> 5, lane = tid & 31;
    const int bh   = blockIdx.y;
    const int b    = bh / NHEADS, h = bh % NHEADS;
    const size_t rowbase = (size_t)(b * SEQ);
    const int hc = h * HDIM;

    const int ldr = tid >> 1;
    const int ldc = (tid & 1) * 32;

    const uint32_t a_row  = (lane & 15);
    const uint32_t a_colb = (lane >> 4) * 16;
    const uint32_t b_row  = (lane & 7) + ((lane >> 4) << 3);
    const uint32_t b_colb = ((lane >> 3) & 1) * 16;
    const uint32_t v_krow  = (lane & 7) + (((lane >> 3) & 1) << 3);
    const uint32_t v_ncolb = (lane >> 4) * 16;

    for (int sidx = 0; sidx < 2; sidx++) {
        const int bx = (sidx == 0) ? (int)blockIdx.x : (31 - (int)blockIdx.x);
        const int q0 = bx * 64;
        const int nk = bx + 1;

        uint32_t qh[4][4], ql[4][4];
        {
            const __nv_bfloat16* src = &g_Qh[(rowbase + q0 + ldr) * DMODEL + hc + ldc];
            #pragma unroll
            for (int i = 0; i < 4; i++)
                *(uint4*)(sm + ldr * ASROW + ldc * 2 + i * 16) = *(const uint4*)(src + i * 8);
            __syncthreads();
            #pragma unroll
            for (int kk = 0; kk < 4; kk++)
                ldsm4(qh[kk], sKh + (wid * 16 + a_row) * ASROW + kk * 32 + a_colb);
            __syncthreads();
            const __nv_bfloat16* src2 = &g_Ql[(rowbase + q0 + ldr) * DMODEL + hc + ldc];
            #pragma unroll
            for (int i = 0; i < 4; i++)
                *(uint4*)(sm + ldr * ASROW + ldc * 2 + i * 16) = *(const uint4*)(src2 + i * 8);
            __syncthreads();
            #pragma unroll
            for (int kk = 0; kk < 4; kk++)
                ldsm4(ql[kk], sKh + (wid * 16 + a_row) * ASROW + kk * 32 + a_colb);
            __syncthreads();
        }

        float o[8][4];
        #pragma unroll
        for (int j = 0; j < 8; j++)
            #pragma unroll
            for (int i = 0; i < 4; i++) o[j][i] = 0.f;
        float m0h = -INFINITY, m1h = -INFINITY, l0 = 0.f, l1 = 0.f;

        for (int kt = 0; kt < nk; kt++) {
            const int kb = kt * 64;
            {
                const size_t srow = (rowbase + kb + ldr) * DMODEL + hc + ldc;
                const uint32_t doff = ldr * ASROW + ldc * 2;
                #pragma unroll
                for (int i = 0; i < 4; i++) {
                    *(uint4*)(sm + 0*64*ASROW + doff + i*16) = *(const uint4*)(&g_Kh[srow] + i*8);
                    *(uint4*)(sm + 1*64*ASROW + doff + i*16) = *(const uint4*)(&g_Kl[srow] + i*8);
                    *(uint4*)(sm + 2*64*ASROW + doff + i*16) = *(const uint4*)(&g_Vh[srow] + i*8);
                    *(uint4*)(sm + 3*64*ASROW + doff + i*16) = *(const uint4*)(&g_Vl[srow] + i*8);
                }
            }
            __syncthreads();

            float sc[8][4];
            #pragma unroll
            for (int j = 0; j < 8; j++)
                #pragma unroll
                for (int i = 0; i < 4; i++) sc[j][i] = 0.f;

            #pragma unroll
            for (int pass = 0; pass < 3; pass++) {
                const uint32_t (*qf)[4] = (pass == 2) ? ql : qh;
                const uint32_t kbase = (pass == 1) ? sKl : sKh;
                #pragma unroll
                for (int kk = 0; kk < 4; kk++) {
                    uint32_t bf[4][4];
                    #pragma unroll
                    for (int nt = 0; nt < 4; nt++)
                        ldsm4(bf[nt], kbase + (nt*16 + b_row) * ASROW + kk*32 + b_colb);
                    #pragma unroll
                    for (int nt = 0; nt < 4; nt++) {
                        mma16816(sc[2*nt],   qf[kk], bf[nt][0], bf[nt][1]);
                        mma16816(sc[2*nt+1], qf[kk], bf[nt][2], bf[nt][3]);
                    }
                }
            }

            const int r0 = q0 + wid*16 + (lane >> 2);
            const int r1 = r0 + 8;
            if (kt == nk - 1) {
                #pragma unroll
                for (int j = 0; j < 8; j++) {
                    const int c0 = kb + j*8 + (lane & 3)*2;
                    if (c0     > r0) sc[j][0] = -1e30f;
                    if (c0 + 1 > r0) sc[j][1] = -1e30f;
                    if (c0     > r1) sc[j][2] = -1e30f;
                    if (c0 + 1 > r1) sc[j][3] = -1e30f;
                }
            }

            float mx0 = -INFINITY, mx1 = -INFINITY;
            #pragma unroll
            for (int j = 0; j < 8; j++) {
                mx0 = fmaxf(mx0, fmaxf(sc[j][0], sc[j][1]));
                mx1 = fmaxf(mx1, fmaxf(sc[j][2], sc[j][3]));
            }
            mx0 = fmaxf(mx0, __shfl_xor_sync(0xffffffffu, mx0, 1));
            mx0 = fmaxf(mx0, __shfl_xor_sync(0xffffffffu, mx0, 2));
            mx1 = fmaxf(mx1, __shfl_xor_sync(0xffffffffu, mx1, 1));
            mx1 = fmaxf(mx1, __shfl_xor_sync(0xffffffffu, mx1, 2));
            const float nm0 = fmaxf(m0h, mx0), nm1 = fmaxf(m1h, mx1);
            const float cr0 = __expf(m0h - nm0), cr1 = __expf(m1h - nm1);
            m0h = nm0; m1h = nm1;
            l0 *= cr0; l1 *= cr1;
            #pragma unroll
            for (int j = 0; j < 8; j++) {
                o[j][0] *= cr0; o[j][1] *= cr0;
                o[j][2] *= cr1; o[j][3] *= cr1;
            }
            #pragma unroll
            for (int j = 0; j < 8; j++) {
                sc[j][0] = __expf(sc[j][0] - nm0);
                sc[j][1] = __expf(sc[j][1] - nm0);
                sc[j][2] = __expf(sc[j][2] - nm1);
                sc[j][3] = __expf(sc[j][3] - nm1);
                l0 += sc[j][0] + sc[j][1];
                l1 += sc[j][2] + sc[j][3];
            }

            uint32_t ph[4][4], pl[4][4];
            #pragma unroll
            for (int ks = 0; ks < 4; ks++) {
                split2(sc[2*ks][0],   sc[2*ks][1],   ph[ks][0], pl[ks][0]);
                split2(sc[2*ks][2],   sc[2*ks][3],   ph[ks][1], pl[ks][1]);
                split2(sc[2*ks+1][0], sc[2*ks+1][1], ph[ks][2], pl[ks][2]);
                split2(sc[2*ks+1][2], sc[2*ks+1][3], ph[ks][3], pl[ks][3]);
            }

            #pragma unroll
            for (int pass = 0; pass < 3; pass++) {
                const uint32_t (*pf)[4] = (pass == 2) ? pl : ph;
                const uint32_t vbase = (pass == 1) ? sVl : sVh;
                #pragma unroll
                for (int ks = 0; ks < 4; ks++) {
                    #pragma unroll
                    for (int nt = 0; nt < 4; nt++) {
                        uint32_t vf[4];
                        ldsm4t(vf, vbase + (ks*16 + v_krow) * ASROW + nt*32 + v_ncolb);
                        mma16816(o[2*nt],   pf[ks], vf[0], vf[1]);
                        mma16816(o[2*nt+1], pf[ks], vf[2], vf[3]);
                    }
                }
            }
            __syncthreads();
        }

        l0 += __shfl_xor_sync(0xffffffffu, l0, 1);
        l0 += __shfl_xor_sync(0xffffffffu, l0, 2);
        l1 += __shfl_xor_sync(0xffffffffu, l1, 1);
        l1 += __shfl_xor_sync(0xffffffffu, l1, 2);
        const float inv0 = 1.f / l0, inv1 = 1.f / l1;
        const size_t row0 = rowbase + q0 + wid*16 + (lane >> 2);
        const size_t row1 = row0 + 8;
        #pragma unroll
        for (int j = 0; j < 8; j++) {
            const int col = hc + j*8 + (lane & 3)*2;
            uint32_t hi, lo;
            split2(o[j][0]*inv0, o[j][1]*inv0, hi, lo);
            *(uint32_t*)&g_AOh[row0 * DMODEL + col] = hi;
            *(uint32_t*)&g_AOl[row0 * DMODEL + col] = lo;
            split2(o[j][2]*inv1, o[j][3]*inv1, hi, lo);
            *(uint32_t*)&g_AOh[row1 * DMODEL + col] = hi;
            *(uint32_t*)&g_AOl[row1 * DMODEL + col] = lo;
        }
        __syncthreads();
    }
}

// ---------------------------------------------------------------------------
extern "C" void kernel_launch(void* const* d_in, const int* in_sizes, int n_in,
                              void* d_out, int out_size)
{
    const float* x  = (const float*)d_in[0];
    const float* wq = (const float*)d_in[1];
    const float* wk = (const float*)d_in[2];
    const float* wv = (const float*)d_in[3];
    const float* wo = (const float*)d_in[4];
    float* out = (float*)d_out;

    __nv_bfloat16 *XH, *XL, *WH, *WL, *QH, *QL, *KH, *KL, *VH, *VL, *AH, *AL;
    cudaGetSymbolAddress((void**)&XH, g_xh);  cudaGetSymbolAddress((void**)&XL, g_xl);
    cudaGetSymbolAddress((void**)&WH, g_wh);  cudaGetSymbolAddress((void**)&WL, g_wl);
    cudaGetSymbolAddress((void**)&QH, g_Qh);  cudaGetSymbolAddress((void**)&QL, g_Ql);
    cudaGetSymbolAddress((void**)&KH, g_Kh);  cudaGetSymbolAddress((void**)&KL, g_Kl);
    cudaGetSymbolAddress((void**)&VH, g_Vh);  cudaGetSymbolAddress((void**)&VL, g_Vl);
    cudaGetSymbolAddress((void**)&AH, g_AOh); cudaGetSymbolAddress((void**)&AL, g_AOl);

    cudaFuncSetAttribute(gemm_db_kernel<1>, cudaFuncAttributeMaxDynamicSharedMemorySize, 2*STAGE_SZ);
    cudaFuncSetAttribute(gemm_db_kernel<0>, cudaFuncAttributeMaxDynamicSharedMemorySize, 2*STAGE_SZ);

    // Launch-count padding so ncu -s 5 -c 1 captures the fused QKV gemm (#6).
    rope_table_kernel<<<(683*32 + 255)/256, 256>>>(0,    683);   // #1
    rope_table_kernel<<<(683*32 + 255)/256, 256>>>(683,  683);   // #2
    rope_table_kernel<<<(682*32 + 255)/256, 256>>>(1366, 682);   // #3
    splitw_kernel<<<(4*(WSZ/4) + 255)/256, 256>>>(wq, wk, wv, wo); // #4
    splitx_kernel<<<((MTOT*DMODEL/4) + 255)/256, 256>>>(x);        // #5

    gemm_db_kernel<1><<<dim3(18, MTOT/128), 256, 2*STAGE_SZ>>>(
        XH, XL, WH, WL, QH, QL, KH, KL, VH, VL, nullptr);          // #6 (ncu)

    attn_mma_kernel<<<dim3(16, BATCH*NHEADS), 128>>>();            // #7

    gemm_db_kernel<0><<<dim3(6, MTOT/128), 256, 2*STAGE_SZ>>>(
        AH, AL, WH + 3*WSZ, WL + 3*WSZ,
        nullptr, nullptr, nullptr, nullptr, nullptr, nullptr, out); // #8
}